// round 3
// baseline (speedup 1.0000x reference)
#include <cuda_runtime.h>
#include <math.h>

// Problem constants
#define Bn 4
#define Nn 4096
#define Kn 16
#define DP 64
#define DM 128
#define NODES (Bn*Nn)            // 16384
#define ATT_OFF (NODES*DP)       // out region first, attn after
#define SCALE_F 0.08838834764831845f

typedef unsigned long long ull;

// Scratch (device globals -- no allocation allowed)
__device__ int   g_idx[NODES*Kn];
__device__ float g_q [NODES*DM];
__device__ float g_k [NODES*DM];
__device__ float g_v [NODES*DM];
__device__ float g_sx[NODES];
__device__ float g_sy[NODES];
__device__ float g_sz[NODES];
__device__ int   g_sid[NODES];

// ---------------------------------------------------------------------------
// f32x2 packed helpers (B300 FFMA2 path -- only reachable via PTX)
// ---------------------------------------------------------------------------
__device__ __forceinline__ ull pk2(float lo, float hi) {
    ull r;
    asm("mov.b64 %0, {%1,%2};" : "=l"(r)
        : "r"(__float_as_uint(lo)), "r"(__float_as_uint(hi)));
    return r;
}
__device__ __forceinline__ ull dup2f(float v) {
    ull r; unsigned u = __float_as_uint(v);
    asm("mov.b64 %0, {%1,%1};" : "=l"(r) : "r"(u));
    return r;
}
__device__ __forceinline__ void fma2(ull& d, ull a, ull b) {
    asm("fma.rn.f32x2 %0, %1, %2, %0;" : "+l"(d) : "l"(a), "l"(b));
}
__device__ __forceinline__ float2 up2(ull v) {
    unsigned lo, hi;
    asm("mov.b64 {%0,%1}, %2;" : "=r"(lo), "=r"(hi) : "l"(v));
    return make_float2(__uint_as_float(lo), __uint_as_float(hi));
}

// ---------------------------------------------------------------------------
// Kernel 0: per-batch bitonic sort of points by x. grid Bn x 1024 threads.
// ---------------------------------------------------------------------------
__global__ void __launch_bounds__(1024) sort_kernel(const float* __restrict__ xyz) {
    __shared__ float skey[Nn];
    __shared__ int   sval[Nn];
    int t = threadIdx.x;
    int b = blockIdx.x;
    const float* base = xyz + (size_t)b * Nn * 3;
    for (int i = t; i < Nn; i += 1024) { skey[i] = base[i*3]; sval[i] = i; }
    __syncthreads();
    for (int k = 2; k <= Nn; k <<= 1) {
        for (int j = k >> 1; j > 0; j >>= 1) {
            for (int e = t; e < Nn; e += 1024) {
                int p = e ^ j;
                if (p > e) {
                    bool up = ((e & k) == 0);
                    float a = skey[e], c = skey[p];
                    if ((a > c) == up) {
                        skey[e] = c; skey[p] = a;
                        int tv = sval[e]; sval[e] = sval[p]; sval[p] = tv;
                    }
                }
            }
            __syncthreads();
        }
    }
    for (int i = t; i < Nn; i += 1024) {
        int id = sval[i];
        g_sx[b*Nn + i] = skey[i];
        g_sy[b*Nn + i] = base[id*3 + 1];
        g_sz[b*Nn + i] = base[id*3 + 2];
        g_sid[b*Nn + i] = id;
    }
}

// ---------------------------------------------------------------------------
// Kernel 1: windowed KNN on sorted-by-x points. grid (32, Bn) x 128 threads.
// Thread = sorted rank r. Two-pointer expansion; stop side when dx^2 > worst.
// Exact distance rounding matches reference; lexicographic (d, idx) ties.
// ---------------------------------------------------------------------------
__global__ void __launch_bounds__(128) knn_kernel(const float* __restrict__ xyz) {
    extern __shared__ float sm3[];
    float* sxs = sm3;
    float* sys = sm3 + Nn;
    float* szs = sm3 + 2*Nn;
    int*   sid = (int*)(sm3 + 3*Nn);
    int t = threadIdx.x;
    int b = blockIdx.y;
    for (int i = t; i < Nn; i += 128) {
        sxs[i] = g_sx[b*Nn + i];
        sys[i] = g_sy[b*Nn + i];
        szs[i] = g_sz[b*Nn + i];
        sid[i] = g_sid[b*Nn + i];
    }
    __syncthreads();

    int r = blockIdx.x * 128 + t;
    float qx = sxs[r], qy = sys[r], qz = szs[r];
    int   qid = sid[r];

    float bd[Kn];
    int   bi[Kn];
#pragma unroll
    for (int m = 0; m < Kn; m++) { bd[m] = 3.4e38f; bi[m] = 0x7fffffff; }
    // self (d computed by formula = 0)
    bd[0] = 0.0f; bi[0] = qid;

    int l = r - 1, rr = r + 1;
    bool al = (l >= 0), ar = (rr < Nn);
    while (al || ar) {
        if (al) {
            float dx = qx - sxs[l];
            float dxx = __fmul_rn(dx, dx);
            if (dxx > bd[Kn-1]) al = false;
            else {
                float dy = qy - sys[l];
                float dz = qz - szs[l];
                float d = __fadd_rn(__fadd_rn(dxx, __fmul_rn(dy,dy)), __fmul_rn(dz,dz));
                int idx = sid[l];
                if (d < bd[Kn-1] || (d == bd[Kn-1] && idx < bi[Kn-1])) {
                    int p = Kn - 1;
                    while (p > 0 && (d < bd[p-1] || (d == bd[p-1] && idx < bi[p-1]))) {
                        bd[p] = bd[p-1]; bi[p] = bi[p-1]; p--;
                    }
                    bd[p] = d; bi[p] = idx;
                }
                if (--l < 0) al = false;
            }
        }
        if (ar) {
            float dx = qx - sxs[rr];
            float dxx = __fmul_rn(dx, dx);
            if (dxx > bd[Kn-1]) ar = false;
            else {
                float dy = qy - sys[rr];
                float dz = qz - szs[rr];
                float d = __fadd_rn(__fadd_rn(dxx, __fmul_rn(dy,dy)), __fmul_rn(dz,dz));
                int idx = sid[rr];
                if (d < bd[Kn-1] || (d == bd[Kn-1] && idx < bi[Kn-1])) {
                    int p = Kn - 1;
                    while (p > 0 && (d < bd[p-1] || (d == bd[p-1] && idx < bi[p-1]))) {
                        bd[p] = bd[p-1]; bi[p] = bi[p-1]; p--;
                    }
                    bd[p] = d; bi[p] = idx;
                }
                if (++rr >= Nn) ar = false;
            }
        }
    }
    int* op = g_idx + ((size_t)(b*Nn) + qid) * Kn;
#pragma unroll
    for (int m = 0; m < Kn; m++) op[m] = bi[m];
}

// ---------------------------------------------------------------------------
// GEMM (proj): out[64 x 128] = A[64 x KD](stride AS) @ W[KD x 128] (+bias, relu)
// 256 threads; each thread 4 rows x 8 cols, packed f32x2 accumulators.
// ---------------------------------------------------------------------------
template<int KD, int AS, bool RELU, bool HASB>
__device__ __forceinline__ void gemm64(const float* __restrict__ sA,
                                       const float* __restrict__ sW,
                                       float* __restrict__ outp,
                                       const float* __restrict__ bias,
                                       int t)
{
    const int tx = t & 15, c0 = tx * 8;
    const int r0 = (t >> 4) * 4;
    ull acc[4][4];
    if (HASB) {
#pragma unroll
        for (int j = 0; j < 4; j++) {
            ull b2 = pk2(bias[c0 + 2*j], bias[c0 + 2*j + 1]);
#pragma unroll
            for (int i = 0; i < 4; i++) acc[i][j] = b2;
        }
    } else {
#pragma unroll
        for (int i = 0; i < 4; i++)
#pragma unroll
            for (int j = 0; j < 4; j++) acc[i][j] = 0ULL;
    }

#pragma unroll 2
    for (int kk = 0; kk < KD; kk += 4) {
        float4 a4[4];
#pragma unroll
        for (int i = 0; i < 4; i++)
            a4[i] = *(const float4*)(sA + (r0 + i) * AS + kk);
#pragma unroll
        for (int kq = 0; kq < 4; kq++) {
            const float* wr = sW + (kk + kq) * 128 + c0;
            ulonglong2 wl = *(const ulonglong2*)(wr);
            ulonglong2 wh = *(const ulonglong2*)(wr + 4);
#pragma unroll
            for (int i = 0; i < 4; i++) {
                float av = (kq == 0) ? a4[i].x : (kq == 1) ? a4[i].y
                         : (kq == 2) ? a4[i].z : a4[i].w;
                ull ad = dup2f(av);
                fma2(acc[i][0], ad, wl.x);
                fma2(acc[i][1], ad, wl.y);
                fma2(acc[i][2], ad, wh.x);
                fma2(acc[i][3], ad, wh.y);
            }
        }
    }

#pragma unroll
    for (int i = 0; i < 4; i++) {
        float2 p0 = up2(acc[i][0]), p1 = up2(acc[i][1]);
        float2 p2 = up2(acc[i][2]), p3 = up2(acc[i][3]);
        float4 lo = make_float4(p0.x, p0.y, p1.x, p1.y);
        float4 hi = make_float4(p2.x, p2.y, p3.x, p3.y);
        if (RELU) {
            lo.x = fmaxf(lo.x, 0.f); lo.y = fmaxf(lo.y, 0.f);
            lo.z = fmaxf(lo.z, 0.f); lo.w = fmaxf(lo.w, 0.f);
            hi.x = fmaxf(hi.x, 0.f); hi.y = fmaxf(hi.y, 0.f);
            hi.z = fmaxf(hi.z, 0.f); hi.w = fmaxf(hi.w, 0.f);
        }
        *(float4*)(outp + (r0 + i) * 128 + c0)     = lo;
        *(float4*)(outp + (r0 + i) * 128 + c0 + 4) = hi;
    }
}

// ---------------------------------------------------------------------------
// Kernel 2: fused projections. 64 rows/CTA, 256 threads, grid 256, 2 CTA/SM.
// ---------------------------------------------------------------------------
__global__ void __launch_bounds__(256, 2) proj_kernel(
    const float* __restrict__ feats,
    const float* __restrict__ fc1_w, const float* __restrict__ fc1_b,
    const float* __restrict__ wq, const float* __restrict__ wk,
    const float* __restrict__ wv)
{
    extern __shared__ float sm2[];
    float* sW = sm2;            // 16384
    float* sA = sm2 + 16384;    // 8192  (x rows, stride 128)
    float* sF = sm2 + 24576;    // 4096  (feature rows, stride 64)
    int t = threadIdx.x;
    int g0 = blockIdx.x * 64;

    for (int o = t; o < 1024; o += 256)
        *(float4*)(sF + o*4) = *(const float4*)(feats + (size_t)g0*64 + o*4);
    for (int o = t; o < 2048; o += 256)
        *(float4*)(sW + o*4) = *(const float4*)(fc1_w + o*4);
    __syncthreads();

    gemm64<64, 64, false, true>(sF, sW, sA, fc1_b, t);
    __syncthreads();

    for (int o = t; o < 4096; o += 256)
        *(float4*)(sW + o*4) = *(const float4*)(wq + o*4);
    __syncthreads();
    gemm64<128, 128, false, false>(sA, sW, g_q + (size_t)g0*128, nullptr, t);
    __syncthreads();
    for (int o = t; o < 4096; o += 256)
        *(float4*)(sW + o*4) = *(const float4*)(wk + o*4);
    __syncthreads();
    gemm64<128, 128, false, false>(sA, sW, g_k + (size_t)g0*128, nullptr, t);
    __syncthreads();
    for (int o = t; o < 4096; o += 256)
        *(float4*)(sW + o*4) = *(const float4*)(wv + o*4);
    __syncthreads();
    gemm64<128, 128, false, false>(sA, sW, g_v + (size_t)g0*128, nullptr, t);
}

// ---------------------------------------------------------------------------
// main kernel building blocks: register-accumulating half-K gemms
// NC=128: thread tile 4 rows x 8 cols; NC=64: 2 rows x 8 cols.
// ---------------------------------------------------------------------------
template<int KD, int AS>
__device__ __forceinline__ void gemm_nc128(ull acc[4][4],
                                           const float* __restrict__ sA,
                                           const float* __restrict__ sW, int t) {
    const int c0 = (t & 15) * 8;
    const int r0 = (t >> 4) * 4;
#pragma unroll 2
    for (int kk = 0; kk < KD; kk += 4) {
        float4 a4[4];
#pragma unroll
        for (int i = 0; i < 4; i++)
            a4[i] = *(const float4*)(sA + (r0 + i) * AS + kk);
#pragma unroll
        for (int kq = 0; kq < 4; kq++) {
            const float* wr = sW + (kk + kq) * 128 + c0;
            ulonglong2 wl = *(const ulonglong2*)(wr);
            ulonglong2 wh = *(const ulonglong2*)(wr + 4);
#pragma unroll
            for (int i = 0; i < 4; i++) {
                float av = (kq == 0) ? a4[i].x : (kq == 1) ? a4[i].y
                         : (kq == 2) ? a4[i].z : a4[i].w;
                ull ad = dup2f(av);
                fma2(acc[i][0], ad, wl.x);
                fma2(acc[i][1], ad, wl.y);
                fma2(acc[i][2], ad, wh.x);
                fma2(acc[i][3], ad, wh.y);
            }
        }
    }
}

// NC=64: A stride AS, W stride 64. Each thread 2 rows x 8 cols.
template<int KD, int AS>
__device__ __forceinline__ void gemm_nc64(ull acc[2][4],
                                          const float* __restrict__ sA,
                                          const float* __restrict__ sW, int t) {
    const int c0 = (t & 7) * 8;
    const int r0 = (t >> 3) * 2;
#pragma unroll 2
    for (int kk = 0; kk < KD; kk += 4) {
        float4 a4[2];
#pragma unroll
        for (int i = 0; i < 2; i++)
            a4[i] = *(const float4*)(sA + (r0 + i) * AS + kk);
#pragma unroll
        for (int kq = 0; kq < 4; kq++) {
            const float* wr = sW + (kk + kq) * 64 + c0;
            ulonglong2 wl = *(const ulonglong2*)(wr);
            ulonglong2 wh = *(const ulonglong2*)(wr + 4);
#pragma unroll
            for (int i = 0; i < 2; i++) {
                float av = (kq == 0) ? a4[i].x : (kq == 1) ? a4[i].y
                         : (kq == 2) ? a4[i].z : a4[i].w;
                ull ad = dup2f(av);
                fma2(acc[i][0], ad, wl.x);
                fma2(acc[i][1], ad, wl.y);
                fma2(acc[i][2], ad, wh.x);
                fma2(acc[i][3], ad, wh.y);
            }
        }
    }
}

__device__ __forceinline__ void init128(ull acc[4][4], const float* __restrict__ bias, int t) {
    const int c0 = (t & 15) * 8;
#pragma unroll
    for (int j = 0; j < 4; j++) {
        ull b2 = pk2(bias[c0 + 2*j], bias[c0 + 2*j + 1]);
#pragma unroll
        for (int i = 0; i < 4; i++) acc[i][j] = b2;
    }
}
__device__ __forceinline__ void store128(float* __restrict__ dst, ull acc[4][4], int t) {
    const int c0 = (t & 15) * 8;
    const int r0 = (t >> 4) * 4;
#pragma unroll
    for (int i = 0; i < 4; i++) {
        float2 p0 = up2(acc[i][0]), p1 = up2(acc[i][1]);
        float2 p2 = up2(acc[i][2]), p3 = up2(acc[i][3]);
        *(float4*)(dst + (r0+i)*128 + c0)     = make_float4(p0.x, p0.y, p1.x, p1.y);
        *(float4*)(dst + (r0+i)*128 + c0 + 4) = make_float4(p2.x, p2.y, p3.x, p3.y);
    }
}
__device__ __forceinline__ void init64(ull acc[2][4], const float* __restrict__ bias, int t) {
    const int c0 = (t & 7) * 8;
#pragma unroll
    for (int j = 0; j < 4; j++) {
        ull b2 = pk2(bias[c0 + 2*j], bias[c0 + 2*j + 1]);
#pragma unroll
        for (int i = 0; i < 2; i++) acc[i][j] = b2;
    }
}
__device__ __forceinline__ void store64_relu(float* __restrict__ dst, ull acc[2][4], int t) {
    const int c0 = (t & 7) * 8;
    const int r0 = (t >> 3) * 2;
#pragma unroll
    for (int i = 0; i < 2; i++) {
        float2 p0 = up2(acc[i][0]), p1 = up2(acc[i][1]);
        float2 p2 = up2(acc[i][2]), p3 = up2(acc[i][3]);
        float4 lo = make_float4(fmaxf(p0.x,0.f), fmaxf(p0.y,0.f), fmaxf(p1.x,0.f), fmaxf(p1.y,0.f));
        float4 hi = make_float4(fmaxf(p2.x,0.f), fmaxf(p2.y,0.f), fmaxf(p3.x,0.f), fmaxf(p3.y,0.f));
        *(float4*)(dst + (r0+i)*64 + c0)     = lo;
        *(float4*)(dst + (r0+i)*64 + c0 + 4) = hi;
    }
}

__device__ __forceinline__ void copy8192(float* __restrict__ dst,
                                         const float* __restrict__ src, int t) {
    for (int o = t; o < 2048; o += 256)
        *(float4*)(dst + o*4) = *(const float4*)(src + o*4);
}
// g1 column-half: dst[k*64 + c] = g1[k*128 + h*64 + c]
__device__ __forceinline__ void copy_g1h(float* __restrict__ dst,
                                         const float* __restrict__ g1, int h, int t) {
    for (int o = t; o < 2048; o += 256) {
        int r = o >> 4, c = (o & 15) * 4;
        *(float4*)(dst + r*64 + c) = *(const float4*)(g1 + r*128 + h*64 + c);
    }
}

// ---------------------------------------------------------------------------
// Kernel 3: fused main. 4 nodes (64 rows) per CTA, 256 threads, 4096 CTAs,
// 2 CTAs/SM (smem 114944 B). Weights staged in 32KB halves; logits & pos
// accumulate in registers across K-halves / hidden-halves.
// ---------------------------------------------------------------------------
__global__ void __launch_bounds__(256, 2) main_kernel(
    const float* __restrict__ xyz, const float* __restrict__ features,
    const float* __restrict__ d1_w, const float* __restrict__ d1_b,
    const float* __restrict__ d2_w, const float* __restrict__ d2_b,
    const float* __restrict__ g1_w, const float* __restrict__ g1_b,
    const float* __restrict__ g2_w, const float* __restrict__ g2_b,
    const float* __restrict__ fc2_w, const float* __restrict__ fc2_b,
    float* __restrict__ out)
{
    extern __shared__ float sm[];
    float* sW   = sm;             // 8192 (32KB) weight half; later sRes overlay
    float* sPos = sm + 8192;      // 8192 ; sRel overlays start until pos stored
    float* sH   = sm + 16384;     // 8192 : t-irrelevant; h, then logits/attn
    float* sX   = sm + 24576;     // 4096 : t1h / a1h (stride 64)
    int*   sIdx = (int*)(sm + 28672); // 64
    float* sRes = sm;             // overlay (sW dead after last gemm)
    float* sRel = sPos;           // overlay (dead before sPos stored)

    int t = threadIdx.x;
    int g0 = blockIdx.x * 4;
    int bbase = g0 & ~(Nn - 1);

    // Phase 0/1: idx + rel
    if (t < 64) {
        int j = g_idx[(size_t)g0*Kn + t];
        sIdx[t] = j;
        int nn = t >> 4;
        const float* pq = xyz + (size_t)(g0 + nn) * 3;
        const float* pj = xyz + (size_t)(bbase + j) * 3;
        sRel[t*3+0] = pq[0] - pj[0];
        sRel[t*3+1] = pq[1] - pj[1];
        sRel[t*3+2] = pq[2] - pj[2];
    }
    __syncthreads();

    // pos = relu(rel@d1+b) @ d2 + d2_b, split over K halves
    ull accP[4][4];
    init128(accP, d2_b, t);
#pragma unroll
    for (int h = 0; h < 2; h++) {
        // t1 half -> sX (64 x 64)
        for (int o4 = t; o4 < 1024; o4 += 256) {
            int r = o4 >> 4, c = (o4 & 15) * 4;
            int gc = h*64 + c;
            float rx = sRel[r*3], ry = sRel[r*3+1], rz = sRel[r*3+2];
            float4 w0 = *(const float4*)(d1_w + gc);
            float4 w1 = *(const float4*)(d1_w + 128 + gc);
            float4 w2 = *(const float4*)(d1_w + 256 + gc);
            float4 bb = *(const float4*)(d1_b + gc);
            float4 v;
            v.x = fmaxf(fmaf(rz,w2.x,fmaf(ry,w1.x,fmaf(rx,w0.x,bb.x))), 0.f);
            v.y = fmaxf(fmaf(rz,w2.y,fmaf(ry,w1.y,fmaf(rx,w0.y,bb.y))), 0.f);
            v.z = fmaxf(fmaf(rz,w2.z,fmaf(ry,w1.z,fmaf(rx,w0.z,bb.z))), 0.f);
            v.w = fmaxf(fmaf(rz,w2.w,fmaf(ry,w1.w,fmaf(rx,w0.w,bb.w))), 0.f);
            *(float4*)(sX + r*64 + c) = v;
        }
        copy8192(sW, d2_w + h*8192, t);
        __syncthreads();
        gemm_nc128<64, 64>(accP, sX, sW, t);
        __syncthreads();
    }
    store128(sPos, accP, t);
    __syncthreads();

    // h = q - k_gather + pos -> sH ; load g1 half0 -> sW (stride 64)
    for (int o4 = t; o4 < 2048; o4 += 256) {
        int r = o4 >> 5, c = (o4 & 31) * 4;
        int nn = r >> 4;
        int j = sIdx[r];
        float4 kv = *(const float4*)(g_k + (size_t)(bbase + j)*128 + c);
        float4 qv = *(const float4*)(g_q + (size_t)(g0 + nn)*128 + c);
        float4 pv = *(const float4*)(sPos + r*128 + c);
        float4 hh;
        hh.x = qv.x - kv.x + pv.x;
        hh.y = qv.y - kv.y + pv.y;
        hh.z = qv.z - kv.z + pv.z;
        hh.w = qv.w - kv.w + pv.w;
        *(float4*)(sH + r*128 + c) = hh;
    }
    copy_g1h(sW, g1_w, 0, t);
    __syncthreads();

    // logits = sum_h relu(h @ g1[:,h*64:] + g1b) @ g2[h*64:,:]  + g2_b
    ull accL[4][4];
    init128(accL, g2_b, t);
#pragma unroll
    for (int h = 0; h < 2; h++) {
        ull accA[2][4];
        init64(accA, g1_b + h*64, t);
        gemm_nc64<128, 128>(accA, sH, sW, t);
        store64_relu(sX, accA, t);
        __syncthreads();
        copy8192(sW, g2_w + h*8192, t);
        __syncthreads();
        gemm_nc128<64, 64>(accL, sX, sW, t);
        __syncthreads();
        if (h == 0) {
            copy_g1h(sW, g1_w, 1, t);
            __syncthreads();
        }
    }
    store128(sH, accL, t);   // logits (h dead)
    __syncthreads();

    // softmax over K per (node, channel); attn in-place in sH; res -> sRes
    for (int p = t; p < 512; p += 256) {
        int nn = p >> 7, c = p & 127;
        int r0n = nn << 4;
        float m = -3.4e38f;
#pragma unroll
        for (int k = 0; k < Kn; k++) m = fmaxf(m, sH[(r0n+k)*128 + c]);
        float e[Kn];
        float ssum = 0.f;
#pragma unroll
        for (int k = 0; k < Kn; k++) {
            e[k] = __expf((sH[(r0n+k)*128 + c] - m) * SCALE_F);
            ssum += e[k];
        }
        float inv = 1.f / ssum;
        float racc = 0.f;
#pragma unroll
        for (int k = 0; k < Kn; k++) {
            float a = e[k] * inv;
            sH[(r0n+k)*128 + c] = a;
            int j = sIdx[r0n + k];
            float vp = g_v[(size_t)(bbase + j)*128 + c] + sPos[(r0n+k)*128 + c];
            racc = fmaf(a, vp, racc);
        }
        sRes[nn*128 + c] = racc;
    }
    __syncthreads();

    // attn out (contiguous block for this CTA)
    {
        float* attn_base = out + (size_t)ATT_OFF + (size_t)g0 * (Kn * DM);
        for (int o4 = t; o4 < 2048; o4 += 256)
            *(float4*)(attn_base + o4*4) = *(const float4*)(sH + o4*4);
    }

    // out = res @ fc2 + fc2_b + pre   (4 nodes x 64 = 256 outputs)
    {
        int nn = t >> 6, d = t & 63;
        float acc = fc2_b[d] + features[(size_t)(g0 + nn)*64 + d];
        const float* rr2 = sRes + nn*128;
#pragma unroll 8
        for (int c = 0; c < 128; c++)
            acc = fmaf(rr2[c], __ldg(fc2_w + c*64 + d), acc);
        out[(size_t)(g0 + nn)*64 + d] = acc;
    }
}

// ---------------------------------------------------------------------------
extern "C" void kernel_launch(void* const* d_in, const int* in_sizes, int n_in,
                              void* d_out, int out_size) {
    const float* xyz   = (const float*)d_in[0];
    const float* feats = (const float*)d_in[1];
    const float* fc1_w = (const float*)d_in[2];
    const float* fc1_b = (const float*)d_in[3];
    const float* fc2_w = (const float*)d_in[4];
    const float* fc2_b = (const float*)d_in[5];
    const float* d1_w  = (const float*)d_in[6];
    const float* d1_b  = (const float*)d_in[7];
    const float* d2_w  = (const float*)d_in[8];
    const float* d2_b  = (const float*)d_in[9];
    const float* g1_w  = (const float*)d_in[10];
    const float* g1_b  = (const float*)d_in[11];
    const float* g2_w  = (const float*)d_in[12];
    const float* g2_b  = (const float*)d_in[13];
    const float* wq    = (const float*)d_in[14];
    const float* wk    = (const float*)d_in[15];
    const float* wv    = (const float*)d_in[16];
    float* outp = (float*)d_out;

    const int SMEM_KNN  = (3*Nn + Nn) * 4;   // 65536 B
    const int SMEM_PROJ = 28672 * 4;         // 114688 B
    const int SMEM_MAIN = 28736 * 4;         // 114944 B
    cudaFuncSetAttribute(knn_kernel,  cudaFuncAttributeMaxDynamicSharedMemorySize, SMEM_KNN);
    cudaFuncSetAttribute(proj_kernel, cudaFuncAttributeMaxDynamicSharedMemorySize, SMEM_PROJ);
    cudaFuncSetAttribute(main_kernel, cudaFuncAttributeMaxDynamicSharedMemorySize, SMEM_MAIN);

    sort_kernel<<<Bn, 1024>>>(xyz);
    knn_kernel<<<dim3(Nn/128, Bn), 128, SMEM_KNN>>>(xyz);
    proj_kernel<<<NODES/64, 256, SMEM_PROJ>>>(feats, fc1_w, fc1_b, wq, wk, wv);
    main_kernel<<<NODES/4, 256, SMEM_MAIN>>>(xyz, feats,
                                             d1_w, d1_b, d2_w, d2_b,
                                             g1_w, g1_b, g2_w, g2_b,
                                             fc2_w, fc2_b, outp);
}

// round 4
// speedup vs baseline: 1.2995x; 1.2995x over previous
#include <cuda_runtime.h>
#include <math.h>

// Problem constants
#define Bn 4
#define Nn 4096
#define Kn 16
#define DP 64
#define DM 128
#define NODES (Bn*Nn)            // 16384
#define ATT_OFF (NODES*DP)       // out region first, attn after
#define SCALE_F 0.08838834764831845f

typedef unsigned long long ull;

// Scratch (device globals -- no allocation allowed)
__device__ int   g_idx[NODES*Kn];
__device__ float g_q [NODES*DM];
__device__ float g_k [NODES*DM];
__device__ float g_v [NODES*DM];
__device__ float g_sx[NODES];
__device__ float g_sy[NODES];
__device__ float g_sz[NODES];
__device__ int   g_sid[NODES];

// ---------------------------------------------------------------------------
// f32x2 packed helpers (B300 FFMA2 path -- only reachable via PTX)
// ---------------------------------------------------------------------------
__device__ __forceinline__ ull pk2(float lo, float hi) {
    ull r;
    asm("mov.b64 %0, {%1,%2};" : "=l"(r)
        : "r"(__float_as_uint(lo)), "r"(__float_as_uint(hi)));
    return r;
}
__device__ __forceinline__ ull dup2f(float v) {
    ull r; unsigned u = __float_as_uint(v);
    asm("mov.b64 %0, {%1,%1};" : "=l"(r) : "r"(u));
    return r;
}
__device__ __forceinline__ void fma2(ull& d, ull a, ull b) {
    asm("fma.rn.f32x2 %0, %1, %2, %0;" : "+l"(d) : "l"(a), "l"(b));
}
__device__ __forceinline__ float2 up2(ull v) {
    unsigned lo, hi;
    asm("mov.b64 {%0,%1}, %2;" : "=r"(lo), "=r"(hi) : "l"(v));
    return make_float2(__uint_as_float(lo), __uint_as_float(hi));
}

// ---------------------------------------------------------------------------
// Kernel 0: per-batch bitonic sort of points by x. grid Bn x 1024 threads.
// ---------------------------------------------------------------------------
__global__ void __launch_bounds__(1024) sort_kernel(const float* __restrict__ xyz) {
    __shared__ float skey[Nn];
    __shared__ int   sval[Nn];
    int t = threadIdx.x;
    int b = blockIdx.x;
    const float* base = xyz + (size_t)b * Nn * 3;
    for (int i = t; i < Nn; i += 1024) { skey[i] = base[i*3]; sval[i] = i; }
    __syncthreads();
    for (int k = 2; k <= Nn; k <<= 1) {
        for (int j = k >> 1; j > 0; j >>= 1) {
            for (int e = t; e < Nn; e += 1024) {
                int p = e ^ j;
                if (p > e) {
                    bool up = ((e & k) == 0);
                    float a = skey[e], c = skey[p];
                    if ((a > c) == up) {
                        skey[e] = c; skey[p] = a;
                        int tv = sval[e]; sval[e] = sval[p]; sval[p] = tv;
                    }
                }
            }
            __syncthreads();
        }
    }
    for (int i = t; i < Nn; i += 1024) {
        int id = sval[i];
        g_sx[b*Nn + i] = skey[i];
        g_sy[b*Nn + i] = base[id*3 + 1];
        g_sz[b*Nn + i] = base[id*3 + 2];
        g_sid[b*Nn + i] = id;
    }
}

// ---------------------------------------------------------------------------
// Kernel 1: windowed KNN on sorted-by-x points. grid (32, Bn) x 128 threads.
// ---------------------------------------------------------------------------
__global__ void __launch_bounds__(128) knn_kernel(const float* __restrict__ xyz) {
    extern __shared__ float sm3[];
    float* sxs = sm3;
    float* sys = sm3 + Nn;
    float* szs = sm3 + 2*Nn;
    int*   sid = (int*)(sm3 + 3*Nn);
    int t = threadIdx.x;
    int b = blockIdx.y;
    for (int i = t; i < Nn; i += 128) {
        sxs[i] = g_sx[b*Nn + i];
        sys[i] = g_sy[b*Nn + i];
        szs[i] = g_sz[b*Nn + i];
        sid[i] = g_sid[b*Nn + i];
    }
    __syncthreads();

    int r = blockIdx.x * 128 + t;
    float qx = sxs[r], qy = sys[r], qz = szs[r];
    int   qid = sid[r];

    float bd[Kn];
    int   bi[Kn];
#pragma unroll
    for (int m = 0; m < Kn; m++) { bd[m] = 3.4e38f; bi[m] = 0x7fffffff; }
    bd[0] = 0.0f; bi[0] = qid;   // self

    int l = r - 1, rr = r + 1;
    bool al = (l >= 0), ar = (rr < Nn);
    while (al || ar) {
        if (al) {
            float dx = qx - sxs[l];
            float dxx = __fmul_rn(dx, dx);
            if (dxx > bd[Kn-1]) al = false;
            else {
                float dy = qy - sys[l];
                float dz = qz - szs[l];
                float d = __fadd_rn(__fadd_rn(dxx, __fmul_rn(dy,dy)), __fmul_rn(dz,dz));
                int idx = sid[l];
                if (d < bd[Kn-1] || (d == bd[Kn-1] && idx < bi[Kn-1])) {
                    int p = Kn - 1;
                    while (p > 0 && (d < bd[p-1] || (d == bd[p-1] && idx < bi[p-1]))) {
                        bd[p] = bd[p-1]; bi[p] = bi[p-1]; p--;
                    }
                    bd[p] = d; bi[p] = idx;
                }
                if (--l < 0) al = false;
            }
        }
        if (ar) {
            float dx = qx - sxs[rr];
            float dxx = __fmul_rn(dx, dx);
            if (dxx > bd[Kn-1]) ar = false;
            else {
                float dy = qy - sys[rr];
                float dz = qz - szs[rr];
                float d = __fadd_rn(__fadd_rn(dxx, __fmul_rn(dy,dy)), __fmul_rn(dz,dz));
                int idx = sid[rr];
                if (d < bd[Kn-1] || (d == bd[Kn-1] && idx < bi[Kn-1])) {
                    int p = Kn - 1;
                    while (p > 0 && (d < bd[p-1] || (d == bd[p-1] && idx < bi[p-1]))) {
                        bd[p] = bd[p-1]; bi[p] = bi[p-1]; p--;
                    }
                    bd[p] = d; bi[p] = idx;
                }
                if (++rr >= Nn) ar = false;
            }
        }
    }
    int* op = g_idx + ((size_t)(b*Nn) + qid) * Kn;
#pragma unroll
    for (int m = 0; m < Kn; m++) op[m] = bi[m];
}

// ---------------------------------------------------------------------------
// Register-accumulating GEMM: 128x128 output, 256 threads, 8 rows x 8 cols
// per thread. acc[8][4] packed f32x2. A stride AS (row-major), W stride 128.
// Per k-quad per thread: 16 LDS.128 vs 128 FFMA2 (2x better than 4x8 tile).
// ---------------------------------------------------------------------------
template<int KD, int AS>
__device__ __forceinline__ void gemm_r8(ull acc[8][4],
                                        const float* __restrict__ sA,
                                        const float* __restrict__ sW, int t) {
    const int c0 = (t & 15) * 8;
    const int r0 = (t >> 4) * 8;
#pragma unroll 2
    for (int kk = 0; kk < KD; kk += 4) {
        float4 a4[8];
#pragma unroll
        for (int i = 0; i < 8; i++)
            a4[i] = *(const float4*)(sA + (r0 + i) * AS + kk);
#pragma unroll
        for (int kq = 0; kq < 4; kq++) {
            const float* wr = sW + (kk + kq) * 128 + c0;
            ulonglong2 wl = *(const ulonglong2*)(wr);
            ulonglong2 wh = *(const ulonglong2*)(wr + 4);
#pragma unroll
            for (int i = 0; i < 8; i++) {
                float av = (kq == 0) ? a4[i].x : (kq == 1) ? a4[i].y
                         : (kq == 2) ? a4[i].z : a4[i].w;
                ull ad = dup2f(av);
                fma2(acc[i][0], ad, wl.x);
                fma2(acc[i][1], ad, wl.y);
                fma2(acc[i][2], ad, wh.x);
                fma2(acc[i][3], ad, wh.y);
            }
        }
    }
}

__device__ __forceinline__ void init_r8(ull acc[8][4], const float* __restrict__ bias, int t) {
    const int c0 = (t & 15) * 8;
#pragma unroll
    for (int j = 0; j < 4; j++) {
        ull b2 = pk2(bias[c0 + 2*j], bias[c0 + 2*j + 1]);
#pragma unroll
        for (int i = 0; i < 8; i++) acc[i][j] = b2;
    }
}
__device__ __forceinline__ void zero_r8(ull acc[8][4]) {
#pragma unroll
    for (int i = 0; i < 8; i++)
#pragma unroll
        for (int j = 0; j < 4; j++) acc[i][j] = 0ULL;
}
template<bool RELU>
__device__ __forceinline__ void store_r8(float* __restrict__ dst, ull acc[8][4], int t) {
    const int c0 = (t & 15) * 8;
    const int r0 = (t >> 4) * 8;
#pragma unroll
    for (int i = 0; i < 8; i++) {
        float2 p0 = up2(acc[i][0]), p1 = up2(acc[i][1]);
        float2 p2 = up2(acc[i][2]), p3 = up2(acc[i][3]);
        float4 lo = make_float4(p0.x, p0.y, p1.x, p1.y);
        float4 hi = make_float4(p2.x, p2.y, p3.x, p3.y);
        if (RELU) {
            lo.x = fmaxf(lo.x, 0.f); lo.y = fmaxf(lo.y, 0.f);
            lo.z = fmaxf(lo.z, 0.f); lo.w = fmaxf(lo.w, 0.f);
            hi.x = fmaxf(hi.x, 0.f); hi.y = fmaxf(hi.y, 0.f);
            hi.z = fmaxf(hi.z, 0.f); hi.w = fmaxf(hi.w, 0.f);
        }
        *(float4*)(dst + (r0 + i) * 128 + c0)     = lo;
        *(float4*)(dst + (r0 + i) * 128 + c0 + 4) = hi;
    }
}

__device__ __forceinline__ void copyW(float* __restrict__ dst,
                                      const float* __restrict__ src, int n4, int t) {
    for (int o = t; o < n4; o += 256)
        *(float4*)(dst + o*4) = *(const float4*)(src + o*4);
}

// ---------------------------------------------------------------------------
// Kernel 2: fused projections. 128 rows/CTA, 256 threads, grid 128.
// ---------------------------------------------------------------------------
__global__ void __launch_bounds__(256) proj_kernel(
    const float* __restrict__ feats,
    const float* __restrict__ fc1_w, const float* __restrict__ fc1_b,
    const float* __restrict__ wq, const float* __restrict__ wk,
    const float* __restrict__ wv)
{
    extern __shared__ float sm2[];
    float* sW = sm2;            // 16384
    float* sX = sm2 + 16384;    // 16384 (x rows, stride 128)
    float* sF = sm2 + 32768;    // 8192  (feature rows, stride 64)
    int t = threadIdx.x;
    int g0 = blockIdx.x * 128;

    copyW(sF, feats + (size_t)g0*64, 2048, t);
    copyW(sW, fc1_w, 2048, t);
    __syncthreads();

    ull acc[8][4];
    init_r8(acc, fc1_b, t);
    gemm_r8<64, 64>(acc, sF, sW, t);
    __syncthreads();
    store_r8<false>(sX, acc, t);
    copyW(sW, wq, 4096, t);
    __syncthreads();

    zero_r8(acc);
    gemm_r8<128, 128>(acc, sX, sW, t);
    store_r8<false>(g_q + (size_t)g0*128, acc, t);
    __syncthreads();
    copyW(sW, wk, 4096, t);
    __syncthreads();

    zero_r8(acc);
    gemm_r8<128, 128>(acc, sX, sW, t);
    store_r8<false>(g_k + (size_t)g0*128, acc, t);
    __syncthreads();
    copyW(sW, wv, 4096, t);
    __syncthreads();

    zero_r8(acc);
    gemm_r8<128, 128>(acc, sX, sW, t);
    store_r8<false>(g_v + (size_t)g0*128, acc, t);
}

// ---------------------------------------------------------------------------
// Kernel 3: fused main. 8 nodes (128 rows) per CTA, 256 threads, 2048 CTAs.
// smem: sW(64KB) + sPos(64KB) + sH(64KB) + rel/idx ~ 196KB, occ 1.
// ---------------------------------------------------------------------------
__global__ void __launch_bounds__(256) main_kernel(
    const float* __restrict__ xyz, const float* __restrict__ features,
    const float* __restrict__ d1_w, const float* __restrict__ d1_b,
    const float* __restrict__ d2_w, const float* __restrict__ d2_b,
    const float* __restrict__ g1_w, const float* __restrict__ g1_b,
    const float* __restrict__ g2_w, const float* __restrict__ g2_b,
    const float* __restrict__ fc2_w, const float* __restrict__ fc2_b,
    float* __restrict__ out)
{
    extern __shared__ float sm[];
    float* sW   = sm;                 // 16384 ; overlays: sRes@0, fc2@+2048
    float* sPos = sm + 16384;         // 16384
    float* sH   = sm + 32768;         // 16384
    float* sRel = sm + 49152;         // 384
    int*   sIdx = (int*)(sm + 49536); // 128
    float* sRes = sW;                 // 1024 floats (sW dead after last gemm)
    float* sFc2 = sW + 2048;          // 8192 floats

    int t = threadIdx.x;
    int g0 = blockIdx.x * 8;
    int bbase = g0 & ~(Nn - 1);

    // P0: idx + rel
    if (t < 128) {
        int j = g_idx[(size_t)g0*Kn + t];
        sIdx[t] = j;
        int nn = t >> 4;
        const float* pq = xyz + (size_t)(g0 + nn) * 3;
        const float* pj = xyz + (size_t)(bbase + j) * 3;
        sRel[t*3+0] = pq[0] - pj[0];
        sRel[t*3+1] = pq[1] - pj[1];
        sRel[t*3+2] = pq[2] - pj[2];
    }
    __syncthreads();

    // P1: t1 = relu(rel@d1 + d1_b) -> sH ; d2 -> sW
    for (int o4 = t; o4 < 4096; o4 += 256) {
        int r = o4 >> 5, c = (o4 & 31) * 4;
        float rx = sRel[r*3], ry = sRel[r*3+1], rz = sRel[r*3+2];
        float4 w0 = *(const float4*)(d1_w + c);
        float4 w1 = *(const float4*)(d1_w + 128 + c);
        float4 w2 = *(const float4*)(d1_w + 256 + c);
        float4 bb = *(const float4*)(d1_b + c);
        float4 v;
        v.x = fmaxf(fmaf(rz,w2.x,fmaf(ry,w1.x,fmaf(rx,w0.x,bb.x))), 0.f);
        v.y = fmaxf(fmaf(rz,w2.y,fmaf(ry,w1.y,fmaf(rx,w0.y,bb.y))), 0.f);
        v.z = fmaxf(fmaf(rz,w2.z,fmaf(ry,w1.z,fmaf(rx,w0.z,bb.z))), 0.f);
        v.w = fmaxf(fmaf(rz,w2.w,fmaf(ry,w1.w,fmaf(rx,w0.w,bb.w))), 0.f);
        *(float4*)(sH + r*128 + c) = v;
    }
    copyW(sW, d2_w, 4096, t);
    __syncthreads();

    // P2: pos = t1 @ d2 + d2_b (regs)
    ull acc[8][4];
    init_r8(acc, d2_b, t);
    gemm_r8<128, 128>(acc, sH, sW, t);
    __syncthreads();

    // P3: store pos ; g1 -> sW
    store_r8<false>(sPos, acc, t);
    copyW(sW, g1_w, 4096, t);
    __syncthreads();

    // P4: h = q - k_gather + pos -> sH
    for (int o4 = t; o4 < 4096; o4 += 256) {
        int r = o4 >> 5, c = (o4 & 31) * 4;
        int nn = r >> 4;
        int j = sIdx[r];
        float4 kv = *(const float4*)(g_k + (size_t)(bbase + j)*128 + c);
        float4 qv = *(const float4*)(g_q + (size_t)(g0 + nn)*128 + c);
        float4 pv = *(const float4*)(sPos + r*128 + c);
        float4 hh;
        hh.x = qv.x - kv.x + pv.x;
        hh.y = qv.y - kv.y + pv.y;
        hh.z = qv.z - kv.z + pv.z;
        hh.w = qv.w - kv.w + pv.w;
        *(float4*)(sH + r*128 + c) = hh;
    }
    __syncthreads();

    // P5: a1 = relu(h @ g1 + g1_b) (regs)
    init_r8(acc, g1_b, t);
    gemm_r8<128, 128>(acc, sH, sW, t);
    __syncthreads();

    // P6: store a1 -> sH ; g2 -> sW
    store_r8<true>(sH, acc, t);
    copyW(sW, g2_w, 4096, t);
    __syncthreads();

    // P7: logits = a1 @ g2 + g2_b (regs)
    init_r8(acc, g2_b, t);
    gemm_r8<128, 128>(acc, sH, sW, t);
    __syncthreads();

    // P8: store logits -> sH ; fc2 -> sFc2 (sW region beyond sRes)
    store_r8<false>(sH, acc, t);
    copyW(sFc2, fc2_w, 2048, t);
    __syncthreads();

    // P9: softmax over K per (node, channel); attn in place; res -> sRes
    for (int p = t; p < 1024; p += 256) {
        int nn = p >> 7, c = p & 127;
        int r0n = nn << 4;
        float m = -3.4e38f;
#pragma unroll
        for (int k = 0; k < Kn; k++) m = fmaxf(m, sH[(r0n+k)*128 + c]);
        float e[Kn];
        float ssum = 0.f;
#pragma unroll
        for (int k = 0; k < Kn; k++) {
            e[k] = __expf((sH[(r0n+k)*128 + c] - m) * SCALE_F);
            ssum += e[k];
        }
        float inv = 1.f / ssum;
        float racc = 0.f;
#pragma unroll
        for (int k = 0; k < Kn; k++) {
            float a = e[k] * inv;
            sH[(r0n+k)*128 + c] = a;
            int j = sIdx[r0n + k];
            float vp = g_v[(size_t)(bbase + j)*128 + c] + sPos[(r0n+k)*128 + c];
            racc = fmaf(a, vp, racc);
        }
        sRes[nn*128 + c] = racc;
    }
    __syncthreads();

    // P10a: attn out (contiguous block for this CTA)
    {
        float* attn_base = out + (size_t)ATT_OFF + (size_t)g0 * (Kn * DM);
        for (int o4 = t; o4 < 4096; o4 += 256)
            *(float4*)(attn_base + o4*4) = *(const float4*)(sH + o4*4);
    }

    // P10b: out = res @ fc2 + fc2_b + pre   (8 nodes x 64 = 512 outputs)
    for (int p = t; p < 512; p += 256) {
        int nn = p >> 6, d = p & 63;
        float a0 = fc2_b[d] + features[(size_t)(g0 + nn)*64 + d];
        const float* rr2 = sRes + nn*128;
#pragma unroll 8
        for (int c = 0; c < 128; c++)
            a0 = fmaf(rr2[c], sFc2[c*64 + d], a0);
        out[(size_t)(g0 + nn)*64 + d] = a0;
    }
}

// ---------------------------------------------------------------------------
extern "C" void kernel_launch(void* const* d_in, const int* in_sizes, int n_in,
                              void* d_out, int out_size) {
    const float* xyz   = (const float*)d_in[0];
    const float* feats = (const float*)d_in[1];
    const float* fc1_w = (const float*)d_in[2];
    const float* fc1_b = (const float*)d_in[3];
    const float* fc2_w = (const float*)d_in[4];
    const float* fc2_b = (const float*)d_in[5];
    const float* d1_w  = (const float*)d_in[6];
    const float* d1_b  = (const float*)d_in[7];
    const float* d2_w  = (const float*)d_in[8];
    const float* d2_b  = (const float*)d_in[9];
    const float* g1_w  = (const float*)d_in[10];
    const float* g1_b  = (const float*)d_in[11];
    const float* g2_w  = (const float*)d_in[12];
    const float* g2_b  = (const float*)d_in[13];
    const float* wq    = (const float*)d_in[14];
    const float* wk    = (const float*)d_in[15];
    const float* wv    = (const float*)d_in[16];
    float* outp = (float*)d_out;

    const int SMEM_KNN  = 4*Nn * 4;          // 65536 B
    const int SMEM_PROJ = 40960 * 4;         // 163840 B
    const int SMEM_MAIN = 49664 * 4;         // 198656 B
    cudaFuncSetAttribute(knn_kernel,  cudaFuncAttributeMaxDynamicSharedMemorySize, SMEM_KNN);
    cudaFuncSetAttribute(proj_kernel, cudaFuncAttributeMaxDynamicSharedMemorySize, SMEM_PROJ);
    cudaFuncSetAttribute(main_kernel, cudaFuncAttributeMaxDynamicSharedMemorySize, SMEM_MAIN);

    sort_kernel<<<Bn, 1024>>>(xyz);
    knn_kernel<<<dim3(Nn/128, Bn), 128, SMEM_KNN>>>(xyz);
    proj_kernel<<<NODES/128, 256, SMEM_PROJ>>>(feats, fc1_w, fc1_b, wq, wk, wv);
    main_kernel<<<NODES/8, 256, SMEM_MAIN>>>(xyz, feats,
                                             d1_w, d1_b, d2_w, d2_b,
                                             g1_w, g1_b, g2_w, g2_b,
                                             fc2_w, fc2_b, outp);
}

// round 5
// speedup vs baseline: 1.3542x; 1.0421x over previous
#include <cuda_runtime.h>
#include <math.h>

// Problem constants
#define Bn 4
#define Nn 4096
#define Kn 16
#define DP 64
#define DM 128
#define NODES (Bn*Nn)            // 16384
#define ATT_OFF (NODES*DP)       // out region first, attn after
#define SCALE_F 0.08838834764831845f

typedef unsigned long long ull;

// Scratch (device globals -- no allocation allowed)
__device__ int   g_idx[NODES*Kn];
__device__ float g_q [NODES*DM];
__device__ float g_k [NODES*DM];
__device__ float g_v [NODES*DM];
// pos scratch: [node][k][DM] = 16384*16*128 floats = 128 MiB (static, allowed)
__device__ float g_posbuf[(size_t)NODES*Kn*DM];
__device__ float g_sx[NODES];
__device__ float g_sy[NODES];
__device__ float g_sz[NODES];
__device__ int   g_sid[NODES];

// ---------------------------------------------------------------------------
// f32x2 packed helpers (B300 FFMA2 path -- only reachable via PTX)
// ---------------------------------------------------------------------------
__device__ __forceinline__ ull pk2(float lo, float hi) {
    ull r;
    asm("mov.b64 %0, {%1,%2};" : "=l"(r)
        : "r"(__float_as_uint(lo)), "r"(__float_as_uint(hi)));
    return r;
}
__device__ __forceinline__ ull dup2f(float v) {
    ull r; unsigned u = __float_as_uint(v);
    asm("mov.b64 %0, {%1,%1};" : "=l"(r) : "r"(u));
    return r;
}
__device__ __forceinline__ void fma2(ull& d, ull a, ull b) {
    asm("fma.rn.f32x2 %0, %1, %2, %0;" : "+l"(d) : "l"(a), "l"(b));
}
__device__ __forceinline__ float2 up2(ull v) {
    unsigned lo, hi;
    asm("mov.b64 {%0,%1}, %2;" : "=r"(lo), "=r"(hi) : "l"(v));
    return make_float2(__uint_as_float(lo), __uint_as_float(hi));
}

// ---------------------------------------------------------------------------
// Kernel 0: per-batch bitonic sort of points by x. grid Bn x 1024 threads.
// ---------------------------------------------------------------------------
__global__ void __launch_bounds__(1024) sort_kernel(const float* __restrict__ xyz) {
    __shared__ float skey[Nn];
    __shared__ int   sval[Nn];
    int t = threadIdx.x;
    int b = blockIdx.x;
    const float* base = xyz + (size_t)b * Nn * 3;
    for (int i = t; i < Nn; i += 1024) { skey[i] = base[i*3]; sval[i] = i; }
    __syncthreads();
    for (int k = 2; k <= Nn; k <<= 1) {
        for (int j = k >> 1; j > 0; j >>= 1) {
            for (int e = t; e < Nn; e += 1024) {
                int p = e ^ j;
                if (p > e) {
                    bool up = ((e & k) == 0);
                    float a = skey[e], c = skey[p];
                    if ((a > c) == up) {
                        skey[e] = c; skey[p] = a;
                        int tv = sval[e]; sval[e] = sval[p]; sval[p] = tv;
                    }
                }
            }
            __syncthreads();
        }
    }
    for (int i = t; i < Nn; i += 1024) {
        int id = sval[i];
        g_sx[b*Nn + i] = skey[i];
        g_sy[b*Nn + i] = base[id*3 + 1];
        g_sz[b*Nn + i] = base[id*3 + 2];
        g_sid[b*Nn + i] = id;
    }
}

// ---------------------------------------------------------------------------
// Kernel 1: windowed KNN on sorted-by-x points, REGISTER top-k (static
// indexing only -- no local memory). grid (32, Bn) x 128 threads.
// ---------------------------------------------------------------------------
__global__ void __launch_bounds__(128) knn_kernel(const float* __restrict__ xyz) {
    extern __shared__ float sm3[];
    float* sxs = sm3;
    float* sys = sm3 + Nn;
    float* szs = sm3 + 2*Nn;
    int*   sid = (int*)(sm3 + 3*Nn);
    int t = threadIdx.x;
    int b = blockIdx.y;
    for (int i = t; i < Nn; i += 128) {
        sxs[i] = g_sx[b*Nn + i];
        sys[i] = g_sy[b*Nn + i];
        szs[i] = g_sz[b*Nn + i];
        sid[i] = g_sid[b*Nn + i];
    }
    __syncthreads();

    int r = blockIdx.x * 128 + t;
    float qx = sxs[r], qy = sys[r], qz = szs[r];
    int   qid = sid[r];

    float bd[Kn];
    int   bi[Kn];
#pragma unroll
    for (int m = 0; m < Kn; m++) { bd[m] = 3.4e38f; bi[m] = 0x7fffffff; }
    bd[0] = 0.0f; bi[0] = qid;   // self

    int l = r - 1, rr = r + 1;
    bool al = (l >= 0), ar = (rr < Nn);
    while (al || ar) {
        if (al) {
            float dx = qx - sxs[l];
            float dxx = __fmul_rn(dx, dx);
            if (dxx > bd[Kn-1]) al = false;
            else {
                float dy = qy - sys[l];
                float dz = qz - szs[l];
                float d = __fadd_rn(__fadd_rn(dxx, __fmul_rn(dy,dy)), __fmul_rn(dz,dz));
                int idx = sid[l];
                if (d < bd[Kn-1] || (d == bd[Kn-1] && idx < bi[Kn-1])) {
                    bd[Kn-1] = d; bi[Kn-1] = idx;
#pragma unroll
                    for (int m = Kn-1; m > 0; m--) {
                        bool sw = (bd[m] < bd[m-1]) ||
                                  (bd[m] == bd[m-1] && bi[m] < bi[m-1]);
                        float td = sw ? bd[m-1] : bd[m];
                        float ts = sw ? bd[m]   : bd[m-1];
                        int   ti = sw ? bi[m-1] : bi[m];
                        int   tj = sw ? bi[m]   : bi[m-1];
                        bd[m] = td; bd[m-1] = ts;
                        bi[m] = ti; bi[m-1] = tj;
                    }
                }
                if (--l < 0) al = false;
            }
        }
        if (ar) {
            float dx = qx - sxs[rr];
            float dxx = __fmul_rn(dx, dx);
            if (dxx > bd[Kn-1]) ar = false;
            else {
                float dy = qy - sys[rr];
                float dz = qz - szs[rr];
                float d = __fadd_rn(__fadd_rn(dxx, __fmul_rn(dy,dy)), __fmul_rn(dz,dz));
                int idx = sid[rr];
                if (d < bd[Kn-1] || (d == bd[Kn-1] && idx < bi[Kn-1])) {
                    bd[Kn-1] = d; bi[Kn-1] = idx;
#pragma unroll
                    for (int m = Kn-1; m > 0; m--) {
                        bool sw = (bd[m] < bd[m-1]) ||
                                  (bd[m] == bd[m-1] && bi[m] < bi[m-1]);
                        float td = sw ? bd[m-1] : bd[m];
                        float ts = sw ? bd[m]   : bd[m-1];
                        int   ti = sw ? bi[m-1] : bi[m];
                        int   tj = sw ? bi[m]   : bi[m-1];
                        bd[m] = td; bd[m-1] = ts;
                        bi[m] = ti; bi[m-1] = tj;
                    }
                }
                if (++rr >= Nn) ar = false;
            }
        }
    }
    int* op = g_idx + ((size_t)(b*Nn) + qid) * Kn;
#pragma unroll
    for (int m = 0; m < Kn; m++) op[m] = bi[m];
}

// ---------------------------------------------------------------------------
// Register-accumulating GEMM: 128-row x 128-col output block, 256 threads,
// 8 rows x 8 cols per thread, packed f32x2 acc. KD k-steps, A row stride AS.
// ---------------------------------------------------------------------------
template<int KD, int AS>
__device__ __forceinline__ void gemm_r8(ull acc[8][4],
                                        const float* __restrict__ sA,
                                        const float* __restrict__ sW, int t) {
    const int c0 = (t & 15) * 8;
    const int r0 = (t >> 4) * 8;
#pragma unroll 2
    for (int kk = 0; kk < KD; kk += 4) {
        float4 a4[8];
#pragma unroll
        for (int i = 0; i < 8; i++)
            a4[i] = *(const float4*)(sA + (r0 + i) * AS + kk);
#pragma unroll
        for (int kq = 0; kq < 4; kq++) {
            const float* wr = sW + (kk + kq) * 128 + c0;
            ulonglong2 wl = *(const ulonglong2*)(wr);
            ulonglong2 wh = *(const ulonglong2*)(wr + 4);
#pragma unroll
            for (int i = 0; i < 8; i++) {
                float av = (kq == 0) ? a4[i].x : (kq == 1) ? a4[i].y
                         : (kq == 2) ? a4[i].z : a4[i].w;
                ull ad = dup2f(av);
                fma2(acc[i][0], ad, wl.x);
                fma2(acc[i][1], ad, wl.y);
                fma2(acc[i][2], ad, wh.x);
                fma2(acc[i][3], ad, wh.y);
            }
        }
    }
}

__device__ __forceinline__ void init_r8(ull acc[8][4], const float* __restrict__ bias, int t) {
    const int c0 = (t & 15) * 8;
#pragma unroll
    for (int j = 0; j < 4; j++) {
        ull b2 = pk2(bias[c0 + 2*j], bias[c0 + 2*j + 1]);
#pragma unroll
        for (int i = 0; i < 8; i++) acc[i][j] = b2;
    }
}
template<bool RELU>
__device__ __forceinline__ void store_r8(float* __restrict__ dst, int stride,
                                         ull acc[8][4], int t) {
    const int c0 = (t & 15) * 8;
    const int r0 = (t >> 4) * 8;
#pragma unroll
    for (int i = 0; i < 8; i++) {
        float2 p0 = up2(acc[i][0]), p1 = up2(acc[i][1]);
        float2 p2 = up2(acc[i][2]), p3 = up2(acc[i][3]);
        float4 lo = make_float4(p0.x, p0.y, p1.x, p1.y);
        float4 hi = make_float4(p2.x, p2.y, p3.x, p3.y);
        if (RELU) {
            lo.x = fmaxf(lo.x, 0.f); lo.y = fmaxf(lo.y, 0.f);
            lo.z = fmaxf(lo.z, 0.f); lo.w = fmaxf(lo.w, 0.f);
            hi.x = fmaxf(hi.x, 0.f); hi.y = fmaxf(hi.y, 0.f);
            hi.z = fmaxf(hi.z, 0.f); hi.w = fmaxf(hi.w, 0.f);
        }
        *(float4*)(dst + (size_t)(r0 + i) * stride + c0)     = lo;
        *(float4*)(dst + (size_t)(r0 + i) * stride + c0 + 4) = hi;
    }
}
// store pos: to smem (in place) AND global scratch
__device__ __forceinline__ void store_r8_pos(float* __restrict__ sdst,
                                             float* __restrict__ gdst,
                                             ull acc[8][4], int t) {
    const int c0 = (t & 15) * 8;
    const int r0 = (t >> 4) * 8;
#pragma unroll
    for (int i = 0; i < 8; i++) {
        float2 p0 = up2(acc[i][0]), p1 = up2(acc[i][1]);
        float2 p2 = up2(acc[i][2]), p3 = up2(acc[i][3]);
        float4 lo = make_float4(p0.x, p0.y, p1.x, p1.y);
        float4 hi = make_float4(p2.x, p2.y, p3.x, p3.y);
        *(float4*)(sdst + (r0 + i) * 128 + c0)     = lo;
        *(float4*)(sdst + (r0 + i) * 128 + c0 + 4) = hi;
        *(float4*)(gdst + (size_t)(r0 + i) * 128 + c0)     = lo;
        *(float4*)(gdst + (size_t)(r0 + i) * 128 + c0 + 4) = hi;
    }
}

__device__ __forceinline__ void copyW(float* __restrict__ dst,
                                      const float* __restrict__ src, int n4, int t) {
    for (int o = t; o < n4; o += 256)
        *(float4*)(dst + o*4) = *(const float4*)(src + o*4);
}

// ---------------------------------------------------------------------------
// Kernel 2: fused projections. 128 rows/CTA, 256 threads, grid 128.
// smem: sW 32KB + sX 64KB = 96KB.
// ---------------------------------------------------------------------------
__global__ void __launch_bounds__(256, 2) proj_kernel(
    const float* __restrict__ feats,
    const float* __restrict__ fc1_w, const float* __restrict__ fc1_b,
    const float* __restrict__ wq, const float* __restrict__ wk,
    const float* __restrict__ wv)
{
    extern __shared__ float sm2[];
    float* sW = sm2;            // 8192 floats (32KB)
    float* sX = sm2 + 8192;     // 16384 floats (64KB)
    int t = threadIdx.x;
    int g0 = blockIdx.x * 128;

    copyW(sX, feats + (size_t)g0*64, 2048, t);   // feats 128x64
    copyW(sW, fc1_w, 2048, t);                   // fc1 64x128 (fits whole)
    __syncthreads();

    ull acc[8][4];
    init_r8(acc, fc1_b, t);
    gemm_r8<64, 64>(acc, sX, sW, t);
    __syncthreads();
    store_r8<false>(sX, 128, acc, t);            // x in place, stride 64 -> 128
    copyW(sW, wq, 2048, t);
    __syncthreads();

    const float* ws[3] = {wq, wk, wv};
    float* outs[3] = {g_q, g_k, g_v};
#pragma unroll
    for (int m = 0; m < 3; m++) {
#pragma unroll
        for (int j = 0; j < 4; j++)
#pragma unroll
            for (int i = 0; i < 8; i++) acc[i][j] = 0ULL;
        gemm_r8<64, 128>(acc, sX, sW, t);
        __syncthreads();
        copyW(sW, ws[m] + 8192, 2048, t);
        __syncthreads();
        gemm_r8<64, 128>(acc, sX + 64, sW, t);
        store_r8<false>(outs[m] + (size_t)g0*128, 128, acc, t);
        if (m < 2) {
            __syncthreads();
            copyW(sW, ws[m+1], 2048, t);
            __syncthreads();
        }
    }
}

// ---------------------------------------------------------------------------
// Kernel 3: fused main. 8 nodes (128 rows) per CTA, 256 threads, 2048 CTAs,
// 2 CTAs/SM. In-place sH chain: t1 -> pos -> h -> a1 -> logits -> attn.
// ---------------------------------------------------------------------------
__global__ void __launch_bounds__(256, 2) main_kernel(
    const float* __restrict__ xyz, const float* __restrict__ features,
    const float* __restrict__ d1_w, const float* __restrict__ d1_b,
    const float* __restrict__ d2_w, const float* __restrict__ d2_b,
    const float* __restrict__ g1_w, const float* __restrict__ g1_b,
    const float* __restrict__ g2_w, const float* __restrict__ g2_b,
    const float* __restrict__ fc2_w, const float* __restrict__ fc2_b,
    float* __restrict__ out)
{
    extern __shared__ float sm[];
    float* sW   = sm;                 // 8192 floats (32KB); fc2 overlay later
    float* sH   = sm + 8192;          // 16384 floats (64KB)
    float* sRel = sm + 24576;         // 384
    int*   sIdx = (int*)(sm + 24960); // 128
    float* sRes = sm + 25088;         // 1024 -> total 26112 floats (104448 B)

    int t = threadIdx.x;
    int g0 = blockIdx.x * 8;
    int bbase = g0 & ~(Nn - 1);
    float* posg = g_posbuf + (size_t)g0 * Kn * DM;

    // P0: idx + rel ; d2 half0 -> sW
    if (t < 128) {
        int j = g_idx[(size_t)g0*Kn + t];
        sIdx[t] = j;
        int nn = t >> 4;
        const float* pq = xyz + (size_t)(g0 + nn) * 3;
        const float* pj = xyz + (size_t)(bbase + j) * 3;
        sRel[t*3+0] = pq[0] - pj[0];
        sRel[t*3+1] = pq[1] - pj[1];
        sRel[t*3+2] = pq[2] - pj[2];
    }
    copyW(sW, d2_w, 2048, t);
    __syncthreads();

    // P1: t1 = relu(rel@d1 + d1_b) -> sH
    for (int o4 = t; o4 < 4096; o4 += 256) {
        int r = o4 >> 5, c = (o4 & 31) * 4;
        float rx = sRel[r*3], ry = sRel[r*3+1], rz = sRel[r*3+2];
        float4 w0 = *(const float4*)(d1_w + c);
        float4 w1 = *(const float4*)(d1_w + 128 + c);
        float4 w2 = *(const float4*)(d1_w + 256 + c);
        float4 bb = *(const float4*)(d1_b + c);
        float4 v;
        v.x = fmaxf(fmaf(rz,w2.x,fmaf(ry,w1.x,fmaf(rx,w0.x,bb.x))), 0.f);
        v.y = fmaxf(fmaf(rz,w2.y,fmaf(ry,w1.y,fmaf(rx,w0.y,bb.y))), 0.f);
        v.z = fmaxf(fmaf(rz,w2.z,fmaf(ry,w1.z,fmaf(rx,w0.z,bb.z))), 0.f);
        v.w = fmaxf(fmaf(rz,w2.w,fmaf(ry,w1.w,fmaf(rx,w0.w,bb.w))), 0.f);
        *(float4*)(sH + r*128 + c) = v;
    }
    __syncthreads();

    ull acc[8][4];

    // P2: pos = t1 @ d2 + d2_b (K halves)
    init_r8(acc, d2_b, t);
    gemm_r8<64, 128>(acc, sH, sW, t);
    __syncthreads();
    copyW(sW, d2_w + 8192, 2048, t);
    __syncthreads();
    gemm_r8<64, 128>(acc, sH + 64, sW, t);
    __syncthreads();

    // P3: pos -> sH in place + g_posbuf
    store_r8_pos(sH, posg, acc, t);
    __syncthreads();

    // P4: h = q - k_gather + pos (in place) ; g1 half0 -> sW
    for (int o4 = t; o4 < 4096; o4 += 256) {
        int r = o4 >> 5, c = (o4 & 31) * 4;
        int nn = r >> 4;
        int j = sIdx[r];
        float4 kv = *(const float4*)(g_k + (size_t)(bbase + j)*128 + c);
        float4 qv = *(const float4*)(g_q + (size_t)(g0 + nn)*128 + c);
        float4 pv = *(const float4*)(sH + r*128 + c);
        float4 hh;
        hh.x = qv.x - kv.x + pv.x;
        hh.y = qv.y - kv.y + pv.y;
        hh.z = qv.z - kv.z + pv.z;
        hh.w = qv.w - kv.w + pv.w;
        *(float4*)(sH + r*128 + c) = hh;
    }
    copyW(sW, g1_w, 2048, t);
    __syncthreads();

    // P5: a1 = relu(h @ g1 + g1_b) (K halves)
    init_r8(acc, g1_b, t);
    gemm_r8<64, 128>(acc, sH, sW, t);
    __syncthreads();
    copyW(sW, g1_w + 8192, 2048, t);
    __syncthreads();
    gemm_r8<64, 128>(acc, sH + 64, sW, t);
    __syncthreads();

    // P6: a1 -> sH in place ; g2 half0 -> sW
    store_r8<true>(sH, 128, acc, t);
    copyW(sW, g2_w, 2048, t);
    __syncthreads();

    // P7: logits = a1 @ g2 + g2_b (K halves)
    init_r8(acc, g2_b, t);
    gemm_r8<64, 128>(acc, sH, sW, t);
    __syncthreads();
    copyW(sW, g2_w + 8192, 2048, t);
    __syncthreads();
    gemm_r8<64, 128>(acc, sH + 64, sW, t);
    __syncthreads();

    // P8: logits -> sH in place ; fc2 -> sW
    store_r8<false>(sH, 128, acc, t);
    copyW(sW, fc2_w, 2048, t);
    __syncthreads();

    // P9: softmax over K per (node, channel); attn in place; res -> sRes
    for (int p = t; p < 1024; p += 256) {
        int nn = p >> 7, c = p & 127;
        int r0n = nn << 4;
        float m = -3.4e38f;
#pragma unroll
        for (int k = 0; k < Kn; k++) m = fmaxf(m, sH[(r0n+k)*128 + c]);
        float e[Kn];
        float ssum = 0.f;
#pragma unroll
        for (int k = 0; k < Kn; k++) {
            e[k] = __expf((sH[(r0n+k)*128 + c] - m) * SCALE_F);
            ssum += e[k];
        }
        float inv = 1.f / ssum;
        float racc = 0.f;
#pragma unroll
        for (int k = 0; k < Kn; k++) {
            float a = e[k] * inv;
            sH[(r0n+k)*128 + c] = a;
            int j = sIdx[r0n + k];
            float vp = g_v[(size_t)(bbase + j)*128 + c] + posg[(size_t)(r0n+k)*128 + c];
            racc = fmaf(a, vp, racc);
        }
        sRes[nn*128 + c] = racc;
    }
    __syncthreads();

    // P10a: attn out
    {
        float* attn_base = out + (size_t)ATT_OFF + (size_t)g0 * (Kn * DM);
        for (int o4 = t; o4 < 4096; o4 += 256)
            *(float4*)(attn_base + o4*4) = *(const float4*)(sH + o4*4);
    }

    // P10b: out = res @ fc2 + fc2_b + pre
    for (int p = t; p < 512; p += 256) {
        int nn = p >> 6, d = p & 63;
        float a0 = fc2_b[d] + features[(size_t)(g0 + nn)*64 + d];
        const float* rr2 = sRes + nn*128;
#pragma unroll 8
        for (int c = 0; c < 128; c++)
            a0 = fmaf(rr2[c], sW[c*64 + d], a0);
        out[(size_t)(g0 + nn)*64 + d] = a0;
    }
}

// ---------------------------------------------------------------------------
extern "C" void kernel_launch(void* const* d_in, const int* in_sizes, int n_in,
                              void* d_out, int out_size) {
    const float* xyz   = (const float*)d_in[0];
    const float* feats = (const float*)d_in[1];
    const float* fc1_w = (const float*)d_in[2];
    const float* fc1_b = (const float*)d_in[3];
    const float* fc2_w = (const float*)d_in[4];
    const float* fc2_b = (const float*)d_in[5];
    const float* d1_w  = (const float*)d_in[6];
    const float* d1_b  = (const float*)d_in[7];
    const float* d2_w  = (const float*)d_in[8];
    const float* d2_b  = (const float*)d_in[9];
    const float* g1_w  = (const float*)d_in[10];
    const float* g1_b  = (const float*)d_in[11];
    const float* g2_w  = (const float*)d_in[12];
    const float* g2_b  = (const float*)d_in[13];
    const float* wq    = (const float*)d_in[14];
    const float* wk    = (const float*)d_in[15];
    const float* wv    = (const float*)d_in[16];
    float* outp = (float*)d_out;

    const int SMEM_KNN  = 4*Nn * 4;          // 65536 B
    const int SMEM_PROJ = 24576 * 4;         // 98304 B
    const int SMEM_MAIN = 26112 * 4;         // 104448 B
    cudaFuncSetAttribute(knn_kernel,  cudaFuncAttributeMaxDynamicSharedMemorySize, SMEM_KNN);
    cudaFuncSetAttribute(proj_kernel, cudaFuncAttributeMaxDynamicSharedMemorySize, SMEM_PROJ);
    cudaFuncSetAttribute(main_kernel, cudaFuncAttributeMaxDynamicSharedMemorySize, SMEM_MAIN);

    sort_kernel<<<Bn, 1024>>>(xyz);
    knn_kernel<<<dim3(Nn/128, Bn), 128, SMEM_KNN>>>(xyz);
    proj_kernel<<<NODES/128, 256, SMEM_PROJ>>>(feats, fc1_w, fc1_b, wq, wk, wv);
    main_kernel<<<NODES/8, 256, SMEM_MAIN>>>(xyz, feats,
                                             d1_w, d1_b, d2_w, d2_b,
                                             g1_w, g1_b, g2_w, g2_b,
                                             fc2_w, fc2_b, outp);
}

// round 6
// speedup vs baseline: 1.7123x; 1.2645x over previous
#include <cuda_runtime.h>
#include <math.h>

// Problem constants
#define Bn 4
#define Nn 4096
#define Kn 16
#define DP 64
#define DM 128
#define NODES (Bn*Nn)            // 16384
#define ATT_OFF (NODES*DP)       // out region first, attn after
#define SCALE_F 0.08838834764831845f

typedef unsigned long long ull;

// Scratch (device globals -- no allocation allowed)
__device__ int    g_idx[NODES*Kn];
__device__ float  g_q [NODES*DM];
__device__ float  g_k [NODES*DM];
__device__ float  g_v [NODES*DM];
__device__ float  g_posbuf[(size_t)NODES*Kn*DM];   // 128 MiB static scratch
__device__ float4 g_sp[NODES];                     // sorted (x,y,z,idx_bits)

// ---------------------------------------------------------------------------
// f32x2 packed helpers (B300 FFMA2 path -- only reachable via PTX)
// ---------------------------------------------------------------------------
__device__ __forceinline__ ull pk2(float lo, float hi) {
    ull r;
    asm("mov.b64 %0, {%1,%2};" : "=l"(r)
        : "r"(__float_as_uint(lo)), "r"(__float_as_uint(hi)));
    return r;
}
__device__ __forceinline__ ull dup2f(float v) {
    ull r; unsigned u = __float_as_uint(v);
    asm("mov.b64 %0, {%1,%1};" : "=l"(r) : "r"(u));
    return r;
}
__device__ __forceinline__ void fma2(ull& d, ull a, ull b) {
    asm("fma.rn.f32x2 %0, %1, %2, %0;" : "+l"(d) : "l"(a), "l"(b));
}
__device__ __forceinline__ float2 up2(ull v) {
    unsigned lo, hi;
    asm("mov.b64 {%0,%1}, %2;" : "=r"(lo), "=r"(hi) : "l"(v));
    return make_float2(__uint_as_float(lo), __uint_as_float(hi));
}

// ---------------------------------------------------------------------------
// Kernel 0: per-batch bitonic sort of points by x. grid Bn x 1024 threads.
// Emits packed float4 (x, y, z, idx_bits) in sorted order.
// ---------------------------------------------------------------------------
__global__ void __launch_bounds__(1024) sort_kernel(const float* __restrict__ xyz) {
    __shared__ float skey[Nn];
    __shared__ int   sval[Nn];
    int t = threadIdx.x;
    int b = blockIdx.x;
    const float* base = xyz + (size_t)b * Nn * 3;
    for (int i = t; i < Nn; i += 1024) { skey[i] = base[i*3]; sval[i] = i; }
    __syncthreads();
    for (int k = 2; k <= Nn; k <<= 1) {
        for (int j = k >> 1; j > 0; j >>= 1) {
            for (int e = t; e < Nn; e += 1024) {
                int p = e ^ j;
                if (p > e) {
                    bool up = ((e & k) == 0);
                    float a = skey[e], c = skey[p];
                    if ((a > c) == up) {
                        skey[e] = c; skey[p] = a;
                        int tv = sval[e]; sval[e] = sval[p]; sval[p] = tv;
                    }
                }
            }
            __syncthreads();
        }
    }
    for (int i = t; i < Nn; i += 1024) {
        int id = sval[i];
        g_sp[b*Nn + i] = make_float4(skey[i], base[id*3 + 1], base[id*3 + 2],
                                     __int_as_float(id));
    }
}

// ---------------------------------------------------------------------------
// Kernel 1: windowed KNN, 2 threads per query (side 0: left incl. self,
// side 1: right), 4-wide speculative chunks, register top-16, packed-key
// merge. grid (32, Bn) x 256 threads (128 queries per CTA).
// ---------------------------------------------------------------------------
__global__ void __launch_bounds__(256) knn_kernel() {
    extern __shared__ char smknn[];
    float4* sp     = (float4*)smknn;                 // 4096 * 16B = 65536
    ull*    smerge = (ull*)(smknn + 65536);          // 128*32*8  = 32768
    int t = threadIdx.x;
    int b = blockIdx.y;
    for (int i = t; i < Nn; i += 256) sp[i] = g_sp[b*Nn + i];
    __syncthreads();

    int lq   = t >> 1;                  // local query 0..127
    int r    = blockIdx.x * 128 + lq;   // sorted rank
    int side = t & 1;

    float4 me = sp[r];
    float qx = me.x, qy = me.y, qz = me.z;
    int qid = __float_as_int(me.w);

    float bd[Kn];
    int   bi[Kn];
#pragma unroll
    for (int m = 0; m < Kn; m++) { bd[m] = 3.4e38f; bi[m] = 0x7fffffff; }
    float worst = 3.4e38f;

    int pos       = (side == 0) ? r      : r + 1;
    int step      = (side == 0) ? -1     : 1;
    int remaining = (side == 0) ? r + 1  : Nn - 1 - r;

    while (remaining > 0) {
        int cnt = remaining < 4 ? remaining : 4;
        float dlist[4];
        int   ilist[4];
        float dxx0 = 0.f;
#pragma unroll
        for (int u = 0; u < 4; u++) {
            if (u < cnt) {
                float4 p = sp[pos + step*u];
                float dx = qx - p.x, dy = qy - p.y, dz = qz - p.z;
                float dxx = __fmul_rn(dx, dx);
                dlist[u] = __fadd_rn(__fadd_rn(dxx, __fmul_rn(dy,dy)),
                                     __fmul_rn(dz,dz));
                ilist[u] = __float_as_int(p.w);
                if (u == 0) dxx0 = dxx;
            } else {
                dlist[u] = 3.4e38f; ilist[u] = 0x7fffffff;
            }
        }
#pragma unroll
        for (int u = 0; u < 4; u++) {
            float d = dlist[u]; int idx = ilist[u];
            if (d < worst || (d == worst && idx < bi[Kn-1])) {
                bd[Kn-1] = d; bi[Kn-1] = idx;
#pragma unroll
                for (int m = Kn-1; m > 0; m--) {
                    bool sw = (bd[m] < bd[m-1]) ||
                              (bd[m] == bd[m-1] && bi[m] < bi[m-1]);
                    float td = sw ? bd[m-1] : bd[m];
                    float ts = sw ? bd[m]   : bd[m-1];
                    int   ti = sw ? bi[m-1] : bi[m];
                    int   tj = sw ? bi[m]   : bi[m-1];
                    bd[m] = td; bd[m-1] = ts;
                    bi[m] = ti; bi[m-1] = tj;
                }
                worst = bd[Kn-1];
            }
        }
        if (dxx0 > worst) break;   // chunk head already too far -> all later too
        pos += step * cnt;
        remaining -= cnt;
    }

    // write packed sorted list
    ull* dst = &smerge[lq*32 + side*16];
#pragma unroll
    for (int m = 0; m < Kn; m++)
        dst[m] = ((ull)__float_as_uint(bd[m]) << 32) | (unsigned)bi[m];
    __syncthreads();

    // side-0 thread merges the two sorted 16-lists
    if (side == 0) {
        const ull* la = &smerge[lq*32];
        const ull* lb = la + 16;
        int ia = 0, ib = 0;
        int* op = g_idx + ((size_t)b*Nn + qid) * Kn;
#pragma unroll
        for (int m = 0; m < Kn; m++) {
            ull ka = (ia < 16) ? la[ia] : 0xFFFFFFFFFFFFFFFFULL;
            ull kb = (ib < 16) ? lb[ib] : 0xFFFFFFFFFFFFFFFFULL;
            if (ka <= kb) { op[m] = (int)(unsigned)(ka & 0xFFFFFFFFu); ia++; }
            else          { op[m] = (int)(unsigned)(kb & 0xFFFFFFFFu); ib++; }
        }
    }
}

// ---------------------------------------------------------------------------
// Register-accumulating GEMM: 128-row x 128-col output block, 256 threads,
// 8 rows x 8 cols per thread, packed f32x2 acc. KD k-steps, A row stride AS.
// ---------------------------------------------------------------------------
template<int KD, int AS>
__device__ __forceinline__ void gemm_r8(ull acc[8][4],
                                        const float* __restrict__ sA,
                                        const float* __restrict__ sW, int t) {
    const int c0 = (t & 15) * 8;
    const int r0 = (t >> 4) * 8;
#pragma unroll 2
    for (int kk = 0; kk < KD; kk += 4) {
        float4 a4[8];
#pragma unroll
        for (int i = 0; i < 8; i++)
            a4[i] = *(const float4*)(sA + (r0 + i) * AS + kk);
#pragma unroll
        for (int kq = 0; kq < 4; kq++) {
            const float* wr = sW + (kk + kq) * 128 + c0;
            ulonglong2 wl = *(const ulonglong2*)(wr);
            ulonglong2 wh = *(const ulonglong2*)(wr + 4);
#pragma unroll
            for (int i = 0; i < 8; i++) {
                float av = (kq == 0) ? a4[i].x : (kq == 1) ? a4[i].y
                         : (kq == 2) ? a4[i].z : a4[i].w;
                ull ad = dup2f(av);
                fma2(acc[i][0], ad, wl.x);
                fma2(acc[i][1], ad, wl.y);
                fma2(acc[i][2], ad, wh.x);
                fma2(acc[i][3], ad, wh.y);
            }
        }
    }
}

__device__ __forceinline__ void init_r8(ull acc[8][4], const float* __restrict__ bias, int t) {
    const int c0 = (t & 15) * 8;
#pragma unroll
    for (int j = 0; j < 4; j++) {
        ull b2 = pk2(bias[c0 + 2*j], bias[c0 + 2*j + 1]);
#pragma unroll
        for (int i = 0; i < 8; i++) acc[i][j] = b2;
    }
}
template<bool RELU>
__device__ __forceinline__ void store_r8(float* __restrict__ dst, int stride,
                                         ull acc[8][4], int t) {
    const int c0 = (t & 15) * 8;
    const int r0 = (t >> 4) * 8;
#pragma unroll
    for (int i = 0; i < 8; i++) {
        float2 p0 = up2(acc[i][0]), p1 = up2(acc[i][1]);
        float2 p2 = up2(acc[i][2]), p3 = up2(acc[i][3]);
        float4 lo = make_float4(p0.x, p0.y, p1.x, p1.y);
        float4 hi = make_float4(p2.x, p2.y, p3.x, p3.y);
        if (RELU) {
            lo.x = fmaxf(lo.x, 0.f); lo.y = fmaxf(lo.y, 0.f);
            lo.z = fmaxf(lo.z, 0.f); lo.w = fmaxf(lo.w, 0.f);
            hi.x = fmaxf(hi.x, 0.f); hi.y = fmaxf(hi.y, 0.f);
            hi.z = fmaxf(hi.z, 0.f); hi.w = fmaxf(hi.w, 0.f);
        }
        *(float4*)(dst + (size_t)(r0 + i) * stride + c0)     = lo;
        *(float4*)(dst + (size_t)(r0 + i) * stride + c0 + 4) = hi;
    }
}
__device__ __forceinline__ void store_r8_pos(float* __restrict__ sdst,
                                             float* __restrict__ gdst,
                                             ull acc[8][4], int t) {
    const int c0 = (t & 15) * 8;
    const int r0 = (t >> 4) * 8;
#pragma unroll
    for (int i = 0; i < 8; i++) {
        float2 p0 = up2(acc[i][0]), p1 = up2(acc[i][1]);
        float2 p2 = up2(acc[i][2]), p3 = up2(acc[i][3]);
        float4 lo = make_float4(p0.x, p0.y, p1.x, p1.y);
        float4 hi = make_float4(p2.x, p2.y, p3.x, p3.y);
        *(float4*)(sdst + (r0 + i) * 128 + c0)     = lo;
        *(float4*)(sdst + (r0 + i) * 128 + c0 + 4) = hi;
        *(float4*)(gdst + (size_t)(r0 + i) * 128 + c0)     = lo;
        *(float4*)(gdst + (size_t)(r0 + i) * 128 + c0 + 4) = hi;
    }
}

__device__ __forceinline__ void copyW(float* __restrict__ dst,
                                      const float* __restrict__ src, int n4, int t) {
    for (int o = t; o < n4; o += 256)
        *(float4*)(dst + o*4) = *(const float4*)(src + o*4);
}

// ---------------------------------------------------------------------------
// Kernel 2: fused projections. 128 rows/CTA, 256 threads, grid 128.
// ---------------------------------------------------------------------------
__global__ void __launch_bounds__(256, 2) proj_kernel(
    const float* __restrict__ feats,
    const float* __restrict__ fc1_w, const float* __restrict__ fc1_b,
    const float* __restrict__ wq, const float* __restrict__ wk,
    const float* __restrict__ wv)
{
    extern __shared__ float sm2[];
    float* sW = sm2;            // 8192 floats (32KB)
    float* sX = sm2 + 8192;     // 16384 floats (64KB)
    int t = threadIdx.x;
    int g0 = blockIdx.x * 128;

    copyW(sX, feats + (size_t)g0*64, 2048, t);
    copyW(sW, fc1_w, 2048, t);
    __syncthreads();

    ull acc[8][4];
    init_r8(acc, fc1_b, t);
    gemm_r8<64, 64>(acc, sX, sW, t);
    __syncthreads();
    store_r8<false>(sX, 128, acc, t);
    copyW(sW, wq, 2048, t);
    __syncthreads();

    const float* ws[3] = {wq, wk, wv};
    float* outs[3] = {g_q, g_k, g_v};
#pragma unroll
    for (int m = 0; m < 3; m++) {
#pragma unroll
        for (int j = 0; j < 4; j++)
#pragma unroll
            for (int i = 0; i < 8; i++) acc[i][j] = 0ULL;
        gemm_r8<64, 128>(acc, sX, sW, t);
        __syncthreads();
        copyW(sW, ws[m] + 8192, 2048, t);
        __syncthreads();
        gemm_r8<64, 128>(acc, sX + 64, sW, t);
        store_r8<false>(outs[m] + (size_t)g0*128, 128, acc, t);
        if (m < 2) {
            __syncthreads();
            copyW(sW, ws[m+1], 2048, t);
            __syncthreads();
        }
    }
}

// ---------------------------------------------------------------------------
// Kernel 3: fused main. 8 nodes (128 rows) per CTA, 256 threads, 2048 CTAs,
// 2 CTAs/SM. In-place sH chain: t1 -> pos -> h -> a1 -> logits -> attn.
// ---------------------------------------------------------------------------
__global__ void __launch_bounds__(256, 2) main_kernel(
    const float* __restrict__ xyz, const float* __restrict__ features,
    const float* __restrict__ d1_w, const float* __restrict__ d1_b,
    const float* __restrict__ d2_w, const float* __restrict__ d2_b,
    const float* __restrict__ g1_w, const float* __restrict__ g1_b,
    const float* __restrict__ g2_w, const float* __restrict__ g2_b,
    const float* __restrict__ fc2_w, const float* __restrict__ fc2_b,
    float* __restrict__ out)
{
    extern __shared__ float sm[];
    float* sW   = sm;                 // 8192 floats (32KB); fc2 overlay later
    float* sH   = sm + 8192;          // 16384 floats (64KB)
    float* sRel = sm + 24576;         // 384
    int*   sIdx = (int*)(sm + 24960); // 128
    float* sRes = sm + 25088;         // 1024 -> total 26112 floats

    int t = threadIdx.x;
    int g0 = blockIdx.x * 8;
    int bbase = g0 & ~(Nn - 1);
    float* posg = g_posbuf + (size_t)g0 * Kn * DM;

    if (t < 128) {
        int j = g_idx[(size_t)g0*Kn + t];
        sIdx[t] = j;
        int nn = t >> 4;
        const float* pq = xyz + (size_t)(g0 + nn) * 3;
        const float* pj = xyz + (size_t)(bbase + j) * 3;
        sRel[t*3+0] = pq[0] - pj[0];
        sRel[t*3+1] = pq[1] - pj[1];
        sRel[t*3+2] = pq[2] - pj[2];
    }
    copyW(sW, d2_w, 2048, t);
    __syncthreads();

    for (int o4 = t; o4 < 4096; o4 += 256) {
        int r = o4 >> 5, c = (o4 & 31) * 4;
        float rx = sRel[r*3], ry = sRel[r*3+1], rz = sRel[r*3+2];
        float4 w0 = *(const float4*)(d1_w + c);
        float4 w1 = *(const float4*)(d1_w + 128 + c);
        float4 w2 = *(const float4*)(d1_w + 256 + c);
        float4 bb = *(const float4*)(d1_b + c);
        float4 v;
        v.x = fmaxf(fmaf(rz,w2.x,fmaf(ry,w1.x,fmaf(rx,w0.x,bb.x))), 0.f);
        v.y = fmaxf(fmaf(rz,w2.y,fmaf(ry,w1.y,fmaf(rx,w0.y,bb.y))), 0.f);
        v.z = fmaxf(fmaf(rz,w2.z,fmaf(ry,w1.z,fmaf(rx,w0.z,bb.z))), 0.f);
        v.w = fmaxf(fmaf(rz,w2.w,fmaf(ry,w1.w,fmaf(rx,w0.w,bb.w))), 0.f);
        *(float4*)(sH + r*128 + c) = v;
    }
    __syncthreads();

    ull acc[8][4];

    init_r8(acc, d2_b, t);
    gemm_r8<64, 128>(acc, sH, sW, t);
    __syncthreads();
    copyW(sW, d2_w + 8192, 2048, t);
    __syncthreads();
    gemm_r8<64, 128>(acc, sH + 64, sW, t);
    __syncthreads();

    store_r8_pos(sH, posg, acc, t);
    __syncthreads();

    for (int o4 = t; o4 < 4096; o4 += 256) {
        int r = o4 >> 5, c = (o4 & 31) * 4;
        int nn = r >> 4;
        int j = sIdx[r];
        float4 kv = *(const float4*)(g_k + (size_t)(bbase + j)*128 + c);
        float4 qv = *(const float4*)(g_q + (size_t)(g0 + nn)*128 + c);
        float4 pv = *(const float4*)(sH + r*128 + c);
        float4 hh;
        hh.x = qv.x - kv.x + pv.x;
        hh.y = qv.y - kv.y + pv.y;
        hh.z = qv.z - kv.z + pv.z;
        hh.w = qv.w - kv.w + pv.w;
        *(float4*)(sH + r*128 + c) = hh;
    }
    copyW(sW, g1_w, 2048, t);
    __syncthreads();

    init_r8(acc, g1_b, t);
    gemm_r8<64, 128>(acc, sH, sW, t);
    __syncthreads();
    copyW(sW, g1_w + 8192, 2048, t);
    __syncthreads();
    gemm_r8<64, 128>(acc, sH + 64, sW, t);
    __syncthreads();

    store_r8<true>(sH, 128, acc, t);
    copyW(sW, g2_w, 2048, t);
    __syncthreads();

    init_r8(acc, g2_b, t);
    gemm_r8<64, 128>(acc, sH, sW, t);
    __syncthreads();
    copyW(sW, g2_w + 8192, 2048, t);
    __syncthreads();
    gemm_r8<64, 128>(acc, sH + 64, sW, t);
    __syncthreads();

    store_r8<false>(sH, 128, acc, t);
    copyW(sW, fc2_w, 2048, t);
    __syncthreads();

    for (int p = t; p < 1024; p += 256) {
        int nn = p >> 7, c = p & 127;
        int r0n = nn << 4;
        float m = -3.4e38f;
#pragma unroll
        for (int k = 0; k < Kn; k++) m = fmaxf(m, sH[(r0n+k)*128 + c]);
        float e[Kn];
        float ssum = 0.f;
#pragma unroll
        for (int k = 0; k < Kn; k++) {
            e[k] = __expf((sH[(r0n+k)*128 + c] - m) * SCALE_F);
            ssum += e[k];
        }
        float inv = 1.f / ssum;
        float racc = 0.f;
#pragma unroll
        for (int k = 0; k < Kn; k++) {
            float a = e[k] * inv;
            sH[(r0n+k)*128 + c] = a;
            int j = sIdx[r0n + k];
            float vp = g_v[(size_t)(bbase + j)*128 + c] + posg[(size_t)(r0n+k)*128 + c];
            racc = fmaf(a, vp, racc);
        }
        sRes[nn*128 + c] = racc;
    }
    __syncthreads();

    {
        float* attn_base = out + (size_t)ATT_OFF + (size_t)g0 * (Kn * DM);
        for (int o4 = t; o4 < 4096; o4 += 256)
            *(float4*)(attn_base + o4*4) = *(const float4*)(sH + o4*4);
    }

    for (int p = t; p < 512; p += 256) {
        int nn = p >> 6, d = p & 63;
        float a0 = fc2_b[d] + features[(size_t)(g0 + nn)*64 + d];
        const float* rr2 = sRes + nn*128;
#pragma unroll 8
        for (int c = 0; c < 128; c++)
            a0 = fmaf(rr2[c], sW[c*64 + d], a0);
        out[(size_t)(g0 + nn)*64 + d] = a0;
    }
}

// ---------------------------------------------------------------------------
extern "C" void kernel_launch(void* const* d_in, const int* in_sizes, int n_in,
                              void* d_out, int out_size) {
    const float* xyz   = (const float*)d_in[0];
    const float* feats = (const float*)d_in[1];
    const float* fc1_w = (const float*)d_in[2];
    const float* fc1_b = (const float*)d_in[3];
    const float* fc2_w = (const float*)d_in[4];
    const float* fc2_b = (const float*)d_in[5];
    const float* d1_w  = (const float*)d_in[6];
    const float* d1_b  = (const float*)d_in[7];
    const float* d2_w  = (const float*)d_in[8];
    const float* d2_b  = (const float*)d_in[9];
    const float* g1_w  = (const float*)d_in[10];
    const float* g1_b  = (const float*)d_in[11];
    const float* g2_w  = (const float*)d_in[12];
    const float* g2_b  = (const float*)d_in[13];
    const float* wq    = (const float*)d_in[14];
    const float* wk    = (const float*)d_in[15];
    const float* wv    = (const float*)d_in[16];
    float* outp = (float*)d_out;

    const int SMEM_KNN  = 65536 + 32768;     // 98304 B
    const int SMEM_PROJ = 24576 * 4;         // 98304 B
    const int SMEM_MAIN = 26112 * 4;         // 104448 B
    cudaFuncSetAttribute(knn_kernel,  cudaFuncAttributeMaxDynamicSharedMemorySize, SMEM_KNN);
    cudaFuncSetAttribute(proj_kernel, cudaFuncAttributeMaxDynamicSharedMemorySize, SMEM_PROJ);
    cudaFuncSetAttribute(main_kernel, cudaFuncAttributeMaxDynamicSharedMemorySize, SMEM_MAIN);

    sort_kernel<<<Bn, 1024>>>(xyz);
    knn_kernel<<<dim3(Nn/128, Bn), 256, SMEM_KNN>>>();
    proj_kernel<<<NODES/128, 256, SMEM_PROJ>>>(feats, fc1_w, fc1_b, wq, wk, wv);
    main_kernel<<<NODES/8, 256, SMEM_MAIN>>>(xyz, feats,
                                             d1_w, d1_b, d2_w, d2_b,
                                             g1_w, g1_b, g2_w, g2_b,
                                             fc2_w, fc2_b, outp);
}